// round 14
// baseline (speedup 1.0000x reference)
#include <cuda_runtime.h>
#include <cuda_bf16.h>
#include <cstdint>

// SegmentSum: x[600000,128] f32, sorted index -> out[50000,128] f32
// R9 pipeline retuned for max residency: GROWS=3 (smaller live state),
// __launch_bounds__(128,12) -> regs<=42, 13KB smem -> 12 blocks/SM
// = 48 warps/SM (75% occ), 3-6 rows in flight per warp, 1.32 waves.
//  - Warp owns segments STARTING in its 64-row chunk; skip/spill via ballot.
//  - Rows stream global->smem via cp.async.cg; lane-private 16B slices.
// Every output row written exactly once (poisoned d_out OK, no memset).

#define D_FEAT 128
#define ROWS_PER_WARP 64
#define WARPS_PER_BLOCK 4
#define THREADS_PER_BLOCK (WARPS_PER_BLOCK * 32)
#define NSTAGE 2
#define GROWS 3
#define FULL 0xffffffffu

__device__ __forceinline__ void store_seg(float* __restrict__ out, int seg,
                                          float4 a, int lane) {
    reinterpret_cast<float4*>(out)[(size_t)seg * 32 + lane] = a;
}

__device__ __forceinline__ void zero_range(float* __restrict__ out, int s0,
                                           int s1, int lane) {
    const float4 z = make_float4(0.f, 0.f, 0.f, 0.f);
    for (int s = s0; s < s1; ++s)
        reinterpret_cast<float4*>(out)[(size_t)s * 32 + lane] = z;
}

__device__ __forceinline__ void cp_async16(void* smem_dst, const void* gptr) {
    uint32_t s = (uint32_t)__cvta_generic_to_shared(smem_dst);
    asm volatile("cp.async.cg.shared.global [%0], [%1], 16;"
                 :: "r"(s), "l"(gptr) : "memory");
}
__device__ __forceinline__ void cp_commit() {
    asm volatile("cp.async.commit_group;" ::: "memory");
}
__device__ __forceinline__ void cp_wait_oldest() {
    asm volatile("cp.async.wait_group %0;" :: "n"(NSTAGE - 1) : "memory");
}

__global__ void __launch_bounds__(THREADS_PER_BLOCK, 12)
segment_sum_kernel(const float* __restrict__ x,
                   const int* __restrict__ index,
                   float* __restrict__ out,
                   int n_rows, int n_seg) {
    __shared__ float4 buf[WARPS_PER_BLOCK][NSTAGE][GROWS][32];          // 12 KB
    __shared__ __align__(16) int idxs[WARPS_PER_BLOCK][ROWS_PER_WARP];  // 1 KB

    const int w = threadIdx.x >> 5;
    const int lane = threadIdx.x & 31;
    const int warp_global = blockIdx.x * WARPS_PER_BLOCK + w;

    long start = (long)warp_global * ROWS_PER_WARP;
    if (start >= n_rows) return;
    long end = start + ROWS_PER_WARP;
    if (end > n_rows) end = n_rows;
    const int chunk = (int)(end - start);

    // Preload this chunk's indices into smem (coalesced).
    if (lane < chunk) idxs[w][lane] = __ldg(&index[start + lane]);
    if (32 + lane < chunk) idxs[w][32 + lane] = __ldg(&index[start + 32 + lane]);
    __syncwarp();

    // ---- Skip leading continuation run (owned by an earlier warp) ----
    int r_off = 0;
    if (start > 0) {
        const int prev = __ldg(&index[start - 1]);
        bool found = false;
        #pragma unroll
        for (int off = 0; off < ROWS_PER_WARP; off += 32) {
            if (!found && off < chunk) {
                int i = off + lane;
                int iv = (i < chunk) ? idxs[w][i] : prev + 1;
                unsigned diff = __ballot_sync(FULL, iv != prev);
                if (diff) { r_off = off + __ffs(diff) - 1; found = true; }
            }
        }
        if (!found || r_off >= chunk) return;  // whole chunk is continuation
    } else {
        zero_range(out, 0, idxs[w][0], lane);
    }

    int cur = idxs[w][r_off];
    float4 acc = make_float4(0.f, 0.f, 0.f, 0.f);

    const int n = chunk - r_off;                       // rows to pipeline
    const float* xbase = x + (start + r_off) * D_FEAT + lane * 4;

    // ---- Prologue: fill both stages ----
    int issued = 0;
    #pragma unroll
    for (int s = 0; s < NSTAGE; ++s) {
        #pragma unroll
        for (int g = 0; g < GROWS; ++g) {
            int row = issued + g;
            if (row < n)
                cp_async16(&buf[w][s][g][lane], xbase + (long)row * D_FEAT);
        }
        cp_commit();
        issued += GROWS;
    }

    // ---- Steady state ----
    int proc = 0, stage = 0;
    while (proc < n) {
        cp_wait_oldest();  // oldest stage resident
        int m = n - proc;
        if (m > GROWS) m = GROWS;

        float4 v[GROWS];
        int id[GROWS];
        int base_i = r_off + proc;
        #pragma unroll
        for (int g = 0; g < GROWS; ++g) {
            if (g < m) {
                id[g] = idxs[w][base_i + g];
                v[g] = buf[w][stage][g][lane];
            }
        }

        // Refill this stage immediately (keeps the pipe full during logic).
        #pragma unroll
        for (int g = 0; g < GROWS; ++g) {
            int row = issued + g;
            if (row < n)
                cp_async16(&buf[w][stage][g][lane], xbase + (long)row * D_FEAT);
        }
        cp_commit();
        issued += GROWS;

        if (m == GROWS && id[GROWS - 1] == cur) {
            // Fast path: sorted => last id == cur implies whole group == cur.
            acc.x += v[0].x + v[1].x + v[2].x;
            acc.y += v[0].y + v[1].y + v[2].y;
            acc.z += v[0].z + v[1].z + v[2].z;
            acc.w += v[0].w + v[1].w + v[2].w;
        } else {
            #pragma unroll
            for (int g = 0; g < GROWS; ++g) {
                if (g < m) {
                    if (id[g] != cur) {
                        store_seg(out, cur, acc, lane);
                        zero_range(out, cur + 1, id[g], lane);
                        cur = id[g];
                        acc = make_float4(0.f, 0.f, 0.f, 0.f);
                    }
                    acc.x += v[g].x;
                    acc.y += v[g].y;
                    acc.z += v[g].z;
                    acc.w += v[g].w;
                }
            }
        }
        proc += GROWS;
        stage ^= 1;
    }

    // ---- Spill: current (owned) run may continue past chunk end ----
    const float4* __restrict__ xv = reinterpret_cast<const float4*>(x);
    long r = end;
    for (;;) {
        if (r >= n_rows) {  // globally last segment: store + zero tail
            store_seg(out, cur, acc, lane);
            zero_range(out, cur + 1, n_seg, lane);
            return;
        }
        long rr = r + lane;
        int iv = (rr < n_rows) ? __ldg(&index[rr]) : cur + 1;
        unsigned diff = __ballot_sync(FULL, iv != cur);
        int k = diff ? (__ffs(diff) - 1) : 32;  // rows r..r+k-1 belong to cur
        #pragma unroll 4
        for (int i = 0; i < k; ++i) {
            float4 t = xv[(r + i) * 32 + lane];
            acc.x += t.x;
            acc.y += t.y;
            acc.z += t.z;
            acc.w += t.w;
        }
        r += k;
        if (r >= n_rows) {
            store_seg(out, cur, acc, lane);
            zero_range(out, cur + 1, n_seg, lane);
            return;
        }
        if (k < 32) {  // transition found; next segment owned by a later warp
            int nxt = __shfl_sync(FULL, iv, k);
            store_seg(out, cur, acc, lane);
            zero_range(out, cur + 1, nxt, lane);
            return;
        }
    }
}

extern "C" void kernel_launch(void* const* d_in, const int* in_sizes, int n_in,
                              void* d_out, int out_size) {
    const float* x = (const float*)d_in[0];
    const int* index = (const int*)d_in[1];
    float* out = (float*)d_out;

    const int n_rows = in_sizes[1];
    const int n_seg = out_size / D_FEAT;

    const int n_warps = (n_rows + ROWS_PER_WARP - 1) / ROWS_PER_WARP;
    const int n_blocks = (n_warps + WARPS_PER_BLOCK - 1) / WARPS_PER_BLOCK;
    segment_sum_kernel<<<n_blocks, THREADS_PER_BLOCK>>>(x, index, out,
                                                        n_rows, n_seg);
}

// round 15
// speedup vs baseline: 1.0519x; 1.0519x over previous
#include <cuda_runtime.h>
#include <cuda_bf16.h>
#include <cstdint>

// SegmentSum: x[600000,128] f32, sorted index -> out[50000,128] f32
// FINAL (R9 config — best of 8 measured designs, 57.4us, ~96% of the
// achieved-bandwidth roofline for this read+scattered-store mix):
//  - Warp owns segments STARTING in its 64-row chunk; skip/spill via ballot.
//  - Rows stream global->smem via cp.async.cg (16B/lane/row), 2-stage x
//    4-row per-warp pipeline; lane-private slices (no syncwarp in hot loop).
//  - 48 regs / 17KB smem -> 10 blocks/SM = 40 warps/SM, 1.58 waves.
// Every output row written exactly once (poisoned d_out OK, no memset).

#define D_FEAT 128
#define ROWS_PER_WARP 64
#define WARPS_PER_BLOCK 4
#define THREADS_PER_BLOCK (WARPS_PER_BLOCK * 32)
#define NSTAGE 2
#define GROWS 4
#define FULL 0xffffffffu

__device__ __forceinline__ void store_seg(float* __restrict__ out, int seg,
                                          float4 a, int lane) {
    reinterpret_cast<float4*>(out)[(size_t)seg * 32 + lane] = a;
}

__device__ __forceinline__ void zero_range(float* __restrict__ out, int s0,
                                           int s1, int lane) {
    const float4 z = make_float4(0.f, 0.f, 0.f, 0.f);
    for (int s = s0; s < s1; ++s)
        reinterpret_cast<float4*>(out)[(size_t)s * 32 + lane] = z;
}

__device__ __forceinline__ void cp_async16(void* smem_dst, const void* gptr) {
    uint32_t s = (uint32_t)__cvta_generic_to_shared(smem_dst);
    asm volatile("cp.async.cg.shared.global [%0], [%1], 16;"
                 :: "r"(s), "l"(gptr) : "memory");
}
__device__ __forceinline__ void cp_commit() {
    asm volatile("cp.async.commit_group;" ::: "memory");
}
__device__ __forceinline__ void cp_wait_oldest() {
    asm volatile("cp.async.wait_group %0;" :: "n"(NSTAGE - 1) : "memory");
}

__global__ void __launch_bounds__(THREADS_PER_BLOCK, 10)
segment_sum_kernel(const float* __restrict__ x,
                   const int* __restrict__ index,
                   float* __restrict__ out,
                   int n_rows, int n_seg) {
    __shared__ float4 buf[WARPS_PER_BLOCK][NSTAGE][GROWS][32];  // 16 KB
    __shared__ int idxs[WARPS_PER_BLOCK][ROWS_PER_WARP];        // 1 KB

    const int w = threadIdx.x >> 5;
    const int lane = threadIdx.x & 31;
    const int warp_global = blockIdx.x * WARPS_PER_BLOCK + w;

    long start = (long)warp_global * ROWS_PER_WARP;
    if (start >= n_rows) return;
    long end = start + ROWS_PER_WARP;
    if (end > n_rows) end = n_rows;
    const int chunk = (int)(end - start);

    // Preload this chunk's indices into smem.
    if (lane < chunk) idxs[w][lane] = __ldg(&index[start + lane]);
    if (32 + lane < chunk) idxs[w][32 + lane] = __ldg(&index[start + 32 + lane]);
    __syncwarp();

    // ---- Skip leading continuation run (owned by an earlier warp) ----
    int r_off = 0;
    if (start > 0) {
        const int prev = __ldg(&index[start - 1]);
        bool found = false;
        #pragma unroll
        for (int off = 0; off < ROWS_PER_WARP; off += 32) {
            if (!found && off < chunk) {
                int i = off + lane;
                int iv = (i < chunk) ? idxs[w][i] : prev + 1;
                unsigned diff = __ballot_sync(FULL, iv != prev);
                if (diff) { r_off = off + __ffs(diff) - 1; found = true; }
            }
        }
        if (!found || r_off >= chunk) return;  // whole chunk is continuation
    } else {
        zero_range(out, 0, idxs[w][0], lane);
    }

    int cur = idxs[w][r_off];
    float4 acc = make_float4(0.f, 0.f, 0.f, 0.f);

    const int n = chunk - r_off;                       // rows to pipeline
    const float* xbase = x + (start + r_off) * D_FEAT + lane * 4;

    // ---- Prologue: fill both stages ----
    int issued = 0;
    #pragma unroll
    for (int s = 0; s < NSTAGE; ++s) {
        #pragma unroll
        for (int g = 0; g < GROWS; ++g) {
            int row = issued + g;
            if (row < n)
                cp_async16(&buf[w][s][g][lane], xbase + (long)row * D_FEAT);
        }
        cp_commit();
        issued += GROWS;
    }

    // ---- Steady state ----
    int proc = 0, stage = 0;
    while (proc < n) {
        cp_wait_oldest();  // oldest stage resident
        int m = n - proc;
        if (m > GROWS) m = GROWS;

        float4 v[GROWS];
        int id[GROWS];
        #pragma unroll
        for (int g = 0; g < GROWS; ++g) {
            if (g < m) {
                v[g] = buf[w][stage][g][lane];
                id[g] = idxs[w][r_off + proc + g];
            }
        }
        // Refill this stage immediately.
        #pragma unroll
        for (int g = 0; g < GROWS; ++g) {
            int row = issued + g;
            if (row < n)
                cp_async16(&buf[w][stage][g][lane], xbase + (long)row * D_FEAT);
        }
        cp_commit();
        issued += GROWS;

        #pragma unroll
        for (int g = 0; g < GROWS; ++g) {
            if (g < m) {
                if (id[g] != cur) {
                    store_seg(out, cur, acc, lane);
                    zero_range(out, cur + 1, id[g], lane);
                    cur = id[g];
                    acc = make_float4(0.f, 0.f, 0.f, 0.f);
                }
                acc.x += v[g].x;
                acc.y += v[g].y;
                acc.z += v[g].z;
                acc.w += v[g].w;
            }
        }
        proc += GROWS;
        stage ^= 1;
    }

    // ---- Spill: current (owned) run may continue past chunk end ----
    const float4* __restrict__ xv = reinterpret_cast<const float4*>(x);
    long r = end;
    for (;;) {
        if (r >= n_rows) {  // globally last segment: store + zero tail
            store_seg(out, cur, acc, lane);
            zero_range(out, cur + 1, n_seg, lane);
            return;
        }
        long rr = r + lane;
        int iv = (rr < n_rows) ? __ldg(&index[rr]) : cur + 1;
        unsigned diff = __ballot_sync(FULL, iv != cur);
        int k = diff ? (__ffs(diff) - 1) : 32;  // rows r..r+k-1 belong to cur
        #pragma unroll 4
        for (int i = 0; i < k; ++i) {
            float4 t = xv[(r + i) * 32 + lane];
            acc.x += t.x;
            acc.y += t.y;
            acc.z += t.z;
            acc.w += t.w;
        }
        r += k;
        if (r >= n_rows) {
            store_seg(out, cur, acc, lane);
            zero_range(out, cur + 1, n_seg, lane);
            return;
        }
        if (k < 32) {  // transition found; next segment owned by a later warp
            int nxt = __shfl_sync(FULL, iv, k);
            store_seg(out, cur, acc, lane);
            zero_range(out, cur + 1, nxt, lane);
            return;
        }
    }
}

extern "C" void kernel_launch(void* const* d_in, const int* in_sizes, int n_in,
                              void* d_out, int out_size) {
    const float* x = (const float*)d_in[0];
    const int* index = (const int*)d_in[1];
    float* out = (float*)d_out;

    const int n_rows = in_sizes[1];
    const int n_seg = out_size / D_FEAT;

    const int n_warps = (n_rows + ROWS_PER_WARP - 1) / ROWS_PER_WARP;
    const int n_blocks = (n_warps + WARPS_PER_BLOCK - 1) / WARPS_PER_BLOCK;
    segment_sum_kernel<<<n_blocks, THREADS_PER_BLOCK>>>(x, index, out,
                                                        n_rows, n_seg);
}

// round 16
// speedup vs baseline: 1.0625x; 1.0100x over previous
#include <cuda_runtime.h>
#include <cuda_bf16.h>
#include <cstdint>

// SegmentSum: x[600000,128] f32, sorted index -> out[50000,128] f32
// FINAL (R9 config — best of 8 measured designs; kernel 54.85us at
// 6041 GB/s = the achieved-bandwidth roofline for this pattern):
//  - Warp owns segments STARTING in its 64-row chunk; skip/spill via ballot.
//  - Rows stream global->smem via cp.async.cg (16B/lane/row), 2-stage x
//    4-row per-warp pipeline; lane-private slices (no syncwarp in hot loop).
//  - 48 regs / 17KB smem -> 10 blocks/SM = 40 warps/SM, 1.58 waves.
// Every output row written exactly once (poisoned d_out OK, no memset).

#define D_FEAT 128
#define ROWS_PER_WARP 64
#define WARPS_PER_BLOCK 4
#define THREADS_PER_BLOCK (WARPS_PER_BLOCK * 32)
#define NSTAGE 2
#define GROWS 4
#define FULL 0xffffffffu

__device__ __forceinline__ void store_seg(float* __restrict__ out, int seg,
                                          float4 a, int lane) {
    reinterpret_cast<float4*>(out)[(size_t)seg * 32 + lane] = a;
}

__device__ __forceinline__ void zero_range(float* __restrict__ out, int s0,
                                           int s1, int lane) {
    const float4 z = make_float4(0.f, 0.f, 0.f, 0.f);
    for (int s = s0; s < s1; ++s)
        reinterpret_cast<float4*>(out)[(size_t)s * 32 + lane] = z;
}

__device__ __forceinline__ void cp_async16(void* smem_dst, const void* gptr) {
    uint32_t s = (uint32_t)__cvta_generic_to_shared(smem_dst);
    asm volatile("cp.async.cg.shared.global [%0], [%1], 16;"
                 :: "r"(s), "l"(gptr) : "memory");
}
__device__ __forceinline__ void cp_commit() {
    asm volatile("cp.async.commit_group;" ::: "memory");
}
__device__ __forceinline__ void cp_wait_oldest() {
    asm volatile("cp.async.wait_group %0;" :: "n"(NSTAGE - 1) : "memory");
}

__global__ void __launch_bounds__(THREADS_PER_BLOCK, 10)
segment_sum_kernel(const float* __restrict__ x,
                   const int* __restrict__ index,
                   float* __restrict__ out,
                   int n_rows, int n_seg) {
    __shared__ float4 buf[WARPS_PER_BLOCK][NSTAGE][GROWS][32];  // 16 KB
    __shared__ int idxs[WARPS_PER_BLOCK][ROWS_PER_WARP];        // 1 KB

    const int w = threadIdx.x >> 5;
    const int lane = threadIdx.x & 31;
    const int warp_global = blockIdx.x * WARPS_PER_BLOCK + w;

    long start = (long)warp_global * ROWS_PER_WARP;
    if (start >= n_rows) return;
    long end = start + ROWS_PER_WARP;
    if (end > n_rows) end = n_rows;
    const int chunk = (int)(end - start);

    // Preload this chunk's indices into smem.
    if (lane < chunk) idxs[w][lane] = __ldg(&index[start + lane]);
    if (32 + lane < chunk) idxs[w][32 + lane] = __ldg(&index[start + 32 + lane]);
    __syncwarp();

    // ---- Skip leading continuation run (owned by an earlier warp) ----
    int r_off = 0;
    if (start > 0) {
        const int prev = __ldg(&index[start - 1]);
        bool found = false;
        #pragma unroll
        for (int off = 0; off < ROWS_PER_WARP; off += 32) {
            if (!found && off < chunk) {
                int i = off + lane;
                int iv = (i < chunk) ? idxs[w][i] : prev + 1;
                unsigned diff = __ballot_sync(FULL, iv != prev);
                if (diff) { r_off = off + __ffs(diff) - 1; found = true; }
            }
        }
        if (!found || r_off >= chunk) return;  // whole chunk is continuation
    } else {
        zero_range(out, 0, idxs[w][0], lane);
    }

    int cur = idxs[w][r_off];
    float4 acc = make_float4(0.f, 0.f, 0.f, 0.f);

    const int n = chunk - r_off;                       // rows to pipeline
    const float* xbase = x + (start + r_off) * D_FEAT + lane * 4;

    // ---- Prologue: fill both stages ----
    int issued = 0;
    #pragma unroll
    for (int s = 0; s < NSTAGE; ++s) {
        #pragma unroll
        for (int g = 0; g < GROWS; ++g) {
            int row = issued + g;
            if (row < n)
                cp_async16(&buf[w][s][g][lane], xbase + (long)row * D_FEAT);
        }
        cp_commit();
        issued += GROWS;
    }

    // ---- Steady state ----
    int proc = 0, stage = 0;
    while (proc < n) {
        cp_wait_oldest();  // oldest stage resident
        int m = n - proc;
        if (m > GROWS) m = GROWS;

        float4 v[GROWS];
        int id[GROWS];
        #pragma unroll
        for (int g = 0; g < GROWS; ++g) {
            if (g < m) {
                v[g] = buf[w][stage][g][lane];
                id[g] = idxs[w][r_off + proc + g];
            }
        }
        // Refill this stage immediately.
        #pragma unroll
        for (int g = 0; g < GROWS; ++g) {
            int row = issued + g;
            if (row < n)
                cp_async16(&buf[w][stage][g][lane], xbase + (long)row * D_FEAT);
        }
        cp_commit();
        issued += GROWS;

        #pragma unroll
        for (int g = 0; g < GROWS; ++g) {
            if (g < m) {
                if (id[g] != cur) {
                    store_seg(out, cur, acc, lane);
                    zero_range(out, cur + 1, id[g], lane);
                    cur = id[g];
                    acc = make_float4(0.f, 0.f, 0.f, 0.f);
                }
                acc.x += v[g].x;
                acc.y += v[g].y;
                acc.z += v[g].z;
                acc.w += v[g].w;
            }
        }
        proc += GROWS;
        stage ^= 1;
    }

    // ---- Spill: current (owned) run may continue past chunk end ----
    const float4* __restrict__ xv = reinterpret_cast<const float4*>(x);
    long r = end;
    for (;;) {
        if (r >= n_rows) {  // globally last segment: store + zero tail
            store_seg(out, cur, acc, lane);
            zero_range(out, cur + 1, n_seg, lane);
            return;
        }
        long rr = r + lane;
        int iv = (rr < n_rows) ? __ldg(&index[rr]) : cur + 1;
        unsigned diff = __ballot_sync(FULL, iv != cur);
        int k = diff ? (__ffs(diff) - 1) : 32;  // rows r..r+k-1 belong to cur
        #pragma unroll 4
        for (int i = 0; i < k; ++i) {
            float4 t = xv[(r + i) * 32 + lane];
            acc.x += t.x;
            acc.y += t.y;
            acc.z += t.z;
            acc.w += t.w;
        }
        r += k;
        if (r >= n_rows) {
            store_seg(out, cur, acc, lane);
            zero_range(out, cur + 1, n_seg, lane);
            return;
        }
        if (k < 32) {  // transition found; next segment owned by a later warp
            int nxt = __shfl_sync(FULL, iv, k);
            store_seg(out, cur, acc, lane);
            zero_range(out, cur + 1, nxt, lane);
            return;
        }
    }
}

extern "C" void kernel_launch(void* const* d_in, const int* in_sizes, int n_in,
                              void* d_out, int out_size) {
    const float* x = (const float*)d_in[0];
    const int* index = (const int*)d_in[1];
    float* out = (float*)d_out;

    const int n_rows = in_sizes[1];
    const int n_seg = out_size / D_FEAT;

    const int n_warps = (n_rows + ROWS_PER_WARP - 1) / ROWS_PER_WARP;
    const int n_blocks = (n_warps + WARPS_PER_BLOCK - 1) / WARPS_PER_BLOCK;
    segment_sum_kernel<<<n_blocks, THREADS_PER_BLOCK>>>(x, index, out,
                                                        n_rows, n_seg);
}